// round 13
// baseline (speedup 1.0000x reference)
#include <cuda_runtime.h>
#include <cuda_fp16.h>
#include <math_constants.h>

#define EMB 32
#define MAXN 200704
#define MAXE 3201024
#define MAXG 512
#define FULL 0xffffffffu

// ---------------- scratch ----------------
__device__ float    g_x[MAXN * EMB];
__device__ __align__(16) __half g_mh[MAXN * EMB];    // messages (fp16)
__device__ float    g_feat[MAXN * EMB];
__device__ float    g_gl[MAXN];           // gate logit
__device__ float    g_al[MAXN];           // a1 logit
__device__ float    g_e[MAXN];
__device__ float    g_xgA[MAXG * EMB];
__device__ float    g_xgB[MAXG * EMB];
__device__ int      g_deg[MAXN];          // zero at load; re-zeroed by k_scan
__device__ int      g_row[MAXN + 1];
__device__ int      g_cur[MAXN];
__device__ int      g_csr[MAXE];          // BYTE offsets (src*64) into g_mh
__device__ int      g_part[1024];
__device__ int      g_gs[MAXG + 1];
__device__ int      g_ctr;
__device__ int      g_rel;                // release flag for spin-scan

__device__ __forceinline__ float lrelu(float v) { return v > 0.f ? v : 0.01f * v; }

__device__ __forceinline__ __half2 hmax2s(__half2 a, int o) {
    unsigned u = __shfl_xor_sync(FULL, *(unsigned*)&a, o);
    return __hmax2(a, *(__half2*)&u);
}

// ---------------- setup: hist || pre || embed+msg0 (grid-partitioned) ----------------
__global__ __launch_bounds__(256) void k_setup(
        const float* __restrict__ nf, const float* __restrict__ We,
        const float* __restrict__ be, const float* __restrict__ Wm,
        const float* __restrict__ bm, const int* __restrict__ ei,
        const int* __restrict__ batch, int N, int E, int G, int eB, int nB, int mB) {
    int b = blockIdx.x;
    int tid = threadIdx.x;
    if (b < eB) {                       // ---- hist (deg starts zero) ----
        int e = b * 256 + tid;
        if (e < E) atomicAdd(&g_deg[ei[E + e]], 1);
        return;
    }
    b -= eB;
    if (b < nB) {                       // ---- pre: graph offsets, zeroing ----
        int n = b * 256 + tid;
        if (n == 0) { g_ctr = 0; g_rel = 0; g_row[N] = E; }
        if (n < G * EMB) { g_xgA[n] = 0.f; g_xgB[n] = 0.f; }
        if (n >= N) return;
        int bb = batch[n];
        int bp = (n == 0) ? -1 : batch[n - 1];
        for (int g = bp + 1; g <= bb; g++) g_gs[g] = n;
        if (n == N - 1) for (int g = bb + 1; g <= G; g++) g_gs[g] = N;
        return;
    }
    b -= nB;                            // ---- fused embed + msg0 ----
    int lane = tid & 31;
    float wE[32], bE[32], wm[32];
#pragma unroll
    for (int k = 0; k < 32; k++) { wE[k] = We[k]; bE[k] = be[k]; wm[k] = Wm[k * 32 + lane]; }
    float bmv = bm[lane];
    int warp = (b * 256 + tid) >> 5;
    int nwarps = mB * 8;
    for (int n = warp; n < N; n += nwarps) {
        float f = __ldg(&nf[n]);
        g_x[n * 32 + lane] = lrelu(f * wE[lane] + bE[lane]);
        float a0 = bmv, a1 = 0.f, a2 = 0.f, a3 = 0.f;
#pragma unroll
        for (int k = 0; k < 32; k += 4) {
            a0 += lrelu(f * wE[k + 0] + bE[k + 0]) * wm[k + 0];
            a1 += lrelu(f * wE[k + 1] + bE[k + 1]) * wm[k + 1];
            a2 += lrelu(f * wE[k + 2] + bE[k + 2]) * wm[k + 2];
            a3 += lrelu(f * wE[k + 3] + bE[k + 3]) * wm[k + 3];
        }
        g_mh[n * 32 + lane] = __float2half(lrelu((a0 + a1) + (a2 + a3)));
    }
}

// ---------------- single-pass scan with wide release ----------------
// Each block scans its 512-chunk locally, posts its total; the LAST-arriving
// block exclusive-scans the <=512 partials and sets g_rel once (wide release,
// not a serial domino). All blocks co-resident: 391 blocks @512thr/16regs.
__global__ __launch_bounds__(512) void k_scan(int N, int nb) {
    __shared__ int sm[512];
    __shared__ int sp[512];
    __shared__ bool last;
    int t = threadIdx.x, b = blockIdx.x;
    int i = b * 512 + t;
    int v = (i < N) ? g_deg[i] : 0;
    sm[t] = v;
    __syncthreads();
    for (int off = 1; off < 512; off <<= 1) {      // inclusive local scan
        int a = (t >= off) ? sm[t - off] : 0;
        __syncthreads();
        sm[t] += a;
        __syncthreads();
    }
    if (t == 0) {
        g_part[b] = sm[511];
        __threadfence();
        int old = atomicAdd(&g_ctr, 1);
        last = (old == nb - 1);
    }
    __syncthreads();
    if (last) {
        // exclusive-scan the partials, publish, release everyone
        int pv = (t < nb) ? g_part[t] : 0;
        sp[t] = pv;
        __syncthreads();
        for (int off = 1; off < 512; off <<= 1) {
            int a = (t >= off) ? sp[t - off] : 0;
            __syncthreads();
            sp[t] += a;
            __syncthreads();
        }
        if (t < nb) g_part[t] = sp[t] - pv;        // exclusive base per chunk
        __threadfence();
        if (t == 0) ((volatile int*)&g_rel)[0] = 1;
    } else {
        if (t == 0) {
            while (((volatile int*)&g_rel)[0] == 0) { }
        }
        __syncthreads();
        __threadfence();
    }
    int base = ((volatile int*)g_part)[b];
    if (i < N) {
        int r = base + sm[t] - v;                  // exclusive
        g_row[i] = r;
        g_cur[i] = r;
        g_deg[i] = 0;                              // ready for next replay
    }
}

__global__ void k_scatter(const int* __restrict__ ei, int E) {
    int e = blockIdx.x * blockDim.x + threadIdx.x;
    if (e >= E) return;
    int s = __ldg(&ei[e]);
    int d = __ldg(&ei[E + e]);
    int pos = atomicAdd(&g_cur[d], 1);
    g_csr[pos] = s << 6;          // byte offset into g_mh (64 B per node row)
}

// ---------------- fused gather-max + update MLP ----------------
// agg = max over in-edges of m[src] (fp16, in regs);
// x = lrelu([x, xg[batch], agg] @ Wa + ba) + x
// Agg broadcast via shared-memory staging; regs capped for 4 blocks/SM.
__global__ __launch_bounds__(128, 4) void k_gathupd(const int* __restrict__ batch,
                                                    const float* __restrict__ Wa,
                                                    const float* __restrict__ ba,
                                                    int N, int cur) {
    __shared__ __align__(16) unsigned sagg[4][16];   // per-warp 64B agg row
    int lane = threadIdx.x & 31;
    int wid = threadIdx.x >> 5;
    float w[96];
#pragma unroll
    for (int k = 0; k < 96; k++) w[k] = Wa[k * 32 + lane];
    float bv = ba[lane];
    const float* xg = cur ? g_xgB : g_xgA;
    int eg = lane >> 2;            // edge slot 0..7
    int ch = lane & 3;             // 16B chunk 0..3 of the 64B message row
    const char* mbase = (const char*)g_mh + ch * 16;

    int warp = (blockIdx.x * blockDim.x + threadIdx.x) >> 5;
    int nwarps = (gridDim.x * blockDim.x) >> 5;
    int chunk = (N + nwarps - 1) / nwarps;
    int n0 = warp * chunk;
    int n1 = min(N, n0 + chunk);
    int gprev = -1;
    float xgacc = 0.f;
    for (int n = n0; n < n1; n++) {
        // ---- gather-max (fp16) ----
        int base = g_row[n];
        int deg = g_row[n + 1] - base;
        __half2 ninf = __float2half2_rn(-CUDART_INF_F);
        __half2 m0 = ninf, m1 = ninf, m2 = ninf, m3 = ninf;
        for (int j0 = 0; j0 < deg; j0 += 8) {
            int j = j0 + eg;
            if (j < deg) {
                int off = __ldg(&g_csr[base + j]);
                uint4 v = *(const uint4*)(mbase + off);
                m0 = __hmax2(m0, *(__half2*)&v.x);
                m1 = __hmax2(m1, *(__half2*)&v.y);
                m2 = __hmax2(m2, *(__half2*)&v.z);
                m3 = __hmax2(m3, *(__half2*)&v.w);
            }
        }
#pragma unroll
        for (int o = 4; o <= 16; o <<= 1) {
            m0 = hmax2s(m0, o); m1 = hmax2s(m1, o);
            m2 = hmax2s(m2, o); m3 = hmax2s(m3, o);
        }
        if (deg == 0) {
            __half2 z = __float2half2_rn(0.f);
            m0 = z; m1 = z; m2 = z; m3 = z;
        }
        // ---- stage agg row in shared (lanes 0..3 hold chunks 0..3) ----
        __syncwarp();
        if (lane < 4) {
            uint4 r;
            r.x = *(unsigned*)&m0; r.y = *(unsigned*)&m1;
            r.z = *(unsigned*)&m2; r.w = *(unsigned*)&m3;
            *(uint4*)&sagg[wid][lane * 4] = r;
        }
        __syncwarp();
        // ---- xg term (hoisted per graph; batch sorted) ----
        int gidx = __ldg(&batch[n]);
        if (gidx != gprev) {
            gprev = gidx;
            const float4* xgr = (const float4*)(xg + gidx * 32);
            float b0 = 0.f, b1 = 0.f, b2 = 0.f, b3 = 0.f;
#pragma unroll
            for (int c = 0; c < 8; c++) {
                float4 v = xgr[c];
                b0 += v.x * w[32 + c * 4 + 0];
                b1 += v.y * w[32 + c * 4 + 1];
                b2 += v.z * w[32 + c * 4 + 2];
                b3 += v.w * w[32 + c * 4 + 3];
            }
            xgacc = (b0 + b1) + (b2 + b3);
        }
        // ---- x block ----
        const float4* xr = (const float4*)(g_x + n * 32);
        float a0 = bv + xgacc, a1 = 0.f, a2 = 0.f, a3 = 0.f;
#pragma unroll
        for (int c = 0; c < 8; c++) {
            float4 v = xr[c];
            a0 += v.x * w[c * 4 + 0];
            a1 += v.y * w[c * 4 + 1];
            a2 += v.z * w[c * 4 + 2];
            a3 += v.w * w[c * 4 + 3];
        }
        float xv = g_x[n * 32 + lane];
        // ---- agg block: broadcast-read the staged row ----
#pragma unroll
        for (int c2 = 0; c2 < 4; c2++) {
            uint4 u = *(const uint4*)&sagg[wid][c2 * 4];
            float2 f0 = __half22float2(*(__half2*)&u.x);
            float2 f1 = __half22float2(*(__half2*)&u.y);
            float2 f2 = __half22float2(*(__half2*)&u.z);
            float2 f3 = __half22float2(*(__half2*)&u.w);
            a0 += f0.x * w[64 + c2 * 8 + 0];
            a1 += f0.y * w[64 + c2 * 8 + 1];
            a2 += f1.x * w[64 + c2 * 8 + 2];
            a3 += f1.y * w[64 + c2 * 8 + 3];
            a0 += f2.x * w[64 + c2 * 8 + 4];
            a1 += f2.y * w[64 + c2 * 8 + 5];
            a2 += f3.x * w[64 + c2 * 8 + 6];
            a3 += f3.y * w[64 + c2 * 8 + 7];
        }
        g_x[n * 32 + lane] = lrelu((a0 + a1) + (a2 + a3)) + xv;
    }
}

// fused: feat = lrelu(x@Wf+bf); gate logit; next-step msg (fp16); optional a1 logit
__global__ __launch_bounds__(128) void k_featmsg(const float* __restrict__ Wg,
                                                 const float* __restrict__ bg,
                                                 const float* __restrict__ Wf,
                                                 const float* __restrict__ bf,
                                                 const float* __restrict__ Wm,
                                                 const float* __restrict__ bm,
                                                 const float* __restrict__ Wa1,
                                                 const float* __restrict__ ba1,
                                                 int N, int do_msg, int do_a1) {
    int lane = threadIdx.x & 31;
    int ch = lane & 7;
    float wf[32], wm[32], wg4[4], wa4[4];
#pragma unroll
    for (int k = 0; k < 32; k++) {
        wf[k] = Wf[k * 32 + lane];
        wm[k] = do_msg ? Wm[k * 32 + lane] : 0.f;
    }
#pragma unroll
    for (int k = 0; k < 4; k++) {
        wg4[k] = Wg[ch * 4 + k];
        wa4[k] = do_a1 ? Wa1[ch * 4 + k] : 0.f;
    }
    float bfv = bf[lane];
    float bmv = do_msg ? bm[lane] : 0.f;
    float bgv = bg[0];
    float ba1v = do_a1 ? ba1[0] : 0.f;
    int warp = (blockIdx.x * blockDim.x + threadIdx.x) >> 5;
    int nwarps = (gridDim.x * blockDim.x) >> 5;
    for (int n = warp; n < N; n += nwarps) {
        const float4* xr = (const float4*)(g_x + n * 32);
        float a0 = bfv, a1 = 0.f, a2 = 0.f, a3 = 0.f;
        float q0 = bmv, q1 = 0.f, q2 = 0.f, q3 = 0.f;
        float p = 0.f, pa = 0.f;
#pragma unroll
        for (int c = 0; c < 8; c++) {
            float4 v = xr[c];
            a0 += v.x * wf[c * 4 + 0];
            a1 += v.y * wf[c * 4 + 1];
            a2 += v.z * wf[c * 4 + 2];
            a3 += v.w * wf[c * 4 + 3];
            if (do_msg) {
                q0 += v.x * wm[c * 4 + 0];
                q1 += v.y * wm[c * 4 + 1];
                q2 += v.z * wm[c * 4 + 2];
                q3 += v.w * wm[c * 4 + 3];
            }
            if (c == ch) {
                p  = v.x * wg4[0] + v.y * wg4[1] + v.z * wg4[2] + v.w * wg4[3];
                if (do_a1)
                    pa = v.x * wa4[0] + v.y * wa4[1] + v.z * wa4[2] + v.w * wa4[3];
            }
        }
        g_feat[n * 32 + lane] = lrelu((a0 + a1) + (a2 + a3));
        if (do_msg)
            g_mh[n * 32 + lane] = __float2half(lrelu((q0 + q1) + (q2 + q3)));
#pragma unroll
        for (int o = 1; o <= 4; o <<= 1) {
            p += __shfl_xor_sync(FULL, p, o);
            if (do_a1) pa += __shfl_xor_sync(FULL, pa, o);
        }
        if (lane == 0) {
            g_gl[n] = p + bgv;
            if (do_a1) g_al[n] = pa + ba1v;
        }
    }
}

// block-per-graph: segment softmax over gate logits + attention pooling + transform
__global__ void k_pooltrans(const float* __restrict__ Wt, const float* __restrict__ bt,
                            int cur) {
    __shared__ float sred[16];
    __shared__ float sfac[16][32];
    __shared__ float smx, sinv;
    __shared__ float spooled[32];
    __shared__ float sxg[32];
    int g = blockIdx.x;
    int tid = threadIdx.x;
    int wid = tid >> 5, lane = tid & 31;
    int s = g_gs[g], e2 = g_gs[g + 1];

    float lmax = -CUDART_INF_F;
    for (int n = s + tid; n < e2; n += 512) lmax = fmaxf(lmax, g_gl[n]);
#pragma unroll
    for (int o = 16; o; o >>= 1) lmax = fmaxf(lmax, __shfl_xor_sync(FULL, lmax, o));
    if (lane == 0) sred[wid] = lmax;
    __syncthreads();
    if (tid == 0) {
        float m = sred[0];
#pragma unroll
        for (int w = 1; w < 16; w++) m = fmaxf(m, sred[w]);
        smx = m;
    }
    __syncthreads();
    float mx = smx;

    float facc = 0.f, se = 0.f;
    for (int n = s + wid; n < e2; n += 16) {
        float ev = __expf(g_gl[n] - mx);
        facc += ev * g_feat[n * 32 + lane];
        if (lane == 0) se += ev;
    }
    sfac[wid][lane] = facc;
    if (lane == 0) sred[wid] = se;
    __syncthreads();
    if (wid == 0) {
        float p = 0.f;
#pragma unroll
        for (int w = 0; w < 16; w++) p += sfac[w][lane];
        spooled[lane] = p;
        if (lane == 0) {
            float t = 0.f;
#pragma unroll
            for (int w = 0; w < 16; w++) t += sred[w];
            sinv = t > 0.f ? 1.f / t : 0.f;
        }
        const float* xgc = cur ? g_xgB : g_xgA;
        sxg[lane] = xgc[g * 32 + lane];
    }
    __syncthreads();

    if (tid < 32) {
        int c = tid;
        float inv = sinv;
        float acc = bt[c];
#pragma unroll
        for (int k = 0; k < 32; k++) acc += (spooled[k] * inv) * Wt[k * 32 + c];
#pragma unroll
        for (int k = 0; k < 32; k++) acc += sxg[k] * Wt[(32 + k) * 32 + c];
        float* xgn = cur ? g_xgA : g_xgB;
        xgn[g * 32 + c] = lrelu(acc) + sxg[c];
    }
}

__global__ void k_headsg(const float* __restrict__ Wv, const float* __restrict__ bv,
                         const float* __restrict__ Wa0, const float* __restrict__ ba0,
                         int G, int cur, float* __restrict__ out) {
    int g = blockIdx.x * blockDim.x + threadIdx.x;
    if (g >= G) return;
    const float* xg = cur ? g_xgB : g_xgA;
    float v = bv[0], l0 = ba0[0], l1 = ba0[1];
#pragma unroll
    for (int k = 0; k < 32; k++) {
        float xx = xg[g * 32 + k];
        v += xx * Wv[k];
        l0 += xx * Wa0[k * 2];
        l1 += xx * Wa0[k * 2 + 1];
    }
    out[g] = v;
    float mxv = fmaxf(l0, l1);
    float e0 = __expf(l0 - mxv), e1 = __expf(l1 - mxv);
    float ssum = e0 + e1;
    out[G + g * 2] = e0 / ssum;
    out[G + g * 2 + 1] = e1 / ssum;
}

// final a1 segment softmax over precomputed logits g_al
__global__ void k_a1(int G, float* __restrict__ out) {
    __shared__ float sred[8];
    __shared__ float smx, sinv;
    int g = blockIdx.x;
    int tid = threadIdx.x;
    int wid = tid >> 5, lane = tid & 31;
    int s = g_gs[g], e2 = g_gs[g + 1];

    float lmax = -CUDART_INF_F;
    for (int n = s + tid; n < e2; n += 256) lmax = fmaxf(lmax, g_al[n]);
#pragma unroll
    for (int o = 16; o; o >>= 1) lmax = fmaxf(lmax, __shfl_xor_sync(FULL, lmax, o));
    if (lane == 0) sred[wid] = lmax;
    __syncthreads();
    if (tid == 0) {
        float m = sred[0];
#pragma unroll
        for (int w = 1; w < 8; w++) m = fmaxf(m, sred[w]);
        smx = m;
    }
    __syncthreads();
    float mx = smx;

    float ps = 0.f;
    for (int n = s + tid; n < e2; n += 256) {
        float ev = __expf(g_al[n] - mx);
        g_e[n] = ev;
        ps += ev;
    }
#pragma unroll
    for (int o = 16; o; o >>= 1) ps += __shfl_xor_sync(FULL, ps, o);
    if (lane == 0) sred[wid] = ps;
    __syncthreads();
    if (tid == 0) {
        float t = 0.f;
#pragma unroll
        for (int w = 0; w < 8; w++) t += sred[w];
        sinv = t > 0.f ? 1.f / t : 0.f;
    }
    __syncthreads();
    float inv = sinv;
    for (int n = s + tid; n < e2; n += 256)
        out[3 * G + n] = g_e[n] * inv;
}

// ---------------- launcher ----------------
extern "C" void kernel_launch(void* const* d_in, const int* in_sizes, int n_in,
                              void* d_out, int out_size) {
    const float* nf   = (const float*)d_in[0];
    const int*   ei   = (const int*)d_in[1];
    const int*   batch= (const int*)d_in[2];
    const float* We   = (const float*)d_in[4];
    const float* be   = (const float*)d_in[5];
    const float* Wm   = (const float*)d_in[6];
    const float* bm   = (const float*)d_in[7];
    const float* Wa   = (const float*)d_in[8];
    const float* ba   = (const float*)d_in[9];
    const float* Wg   = (const float*)d_in[10];
    const float* bg   = (const float*)d_in[11];
    const float* Wf   = (const float*)d_in[12];
    const float* bf   = (const float*)d_in[13];
    const float* Wt   = (const float*)d_in[14];
    const float* bt   = (const float*)d_in[15];
    const float* Wv   = (const float*)d_in[16];
    const float* bv   = (const float*)d_in[17];
    const float* Wa0  = (const float*)d_in[18];
    const float* ba0  = (const float*)d_in[19];
    const float* Wa1  = (const float*)d_in[20];
    const float* ba1  = (const float*)d_in[21];
    float* out = (float*)d_out;

    int N = in_sizes[0];
    int E = in_sizes[1] / 2;
    int G = (out_size - N) / 3;
    int S = in_sizes[6] / (EMB * EMB);

    int eB   = (E + 255) / 256;
    int nB   = (N + 255) / 256;
    int mB   = 296;
    int nsb  = (N + 511) / 512;

    k_setup<<<eB + nB + mB, 256>>>(nf, We, be, Wm, bm, ei, batch, N, E, G, eB, nB, mB);
    k_scan<<<nsb, 512>>>(N, nsb);
    k_scatter<<<eB, 256>>>(ei, E);

    int cur = 0;
    for (int i = 0; i < S; i++) {
        int lastS = (i == S - 1);
        k_gathupd<<<592, 128>>>(batch, Wa + i * 96 * 32, ba + i * 32, N, cur);  // launch #4 on i=0
        k_featmsg<<<740, 128>>>(Wg + i * 32, bg + i, Wf + i * 1024, bf + i * 32,
                                Wm + (lastS ? 0 : (i + 1) * 1024),
                                bm + (lastS ? 0 : (i + 1) * 32),
                                Wa1, ba1, N, lastS ? 0 : 1, lastS ? 1 : 0);
        k_pooltrans<<<G, 512>>>(Wt + i * 64 * 32, bt + i * 32, cur);
        cur ^= 1;
    }

    k_headsg<<<(G + 127) / 128, 128>>>(Wv, bv, Wa0, ba0, G, cur, out);
    k_a1<<<G, 256>>>(G, out);
}

// round 15
// speedup vs baseline: 1.3340x; 1.3340x over previous
#include <cuda_runtime.h>
#include <cuda_fp16.h>
#include <math_constants.h>

#define EMB 32
#define MAXN 200704
#define MAXE 3201024
#define MAXG 512
#define FULL 0xffffffffu

// ---------------- scratch ----------------
__device__ float    g_x[MAXN * EMB];
__device__ __align__(16) __half g_mh[MAXN * EMB];    // messages (fp16)
__device__ float    g_feat[MAXN * EMB];
__device__ float    g_gl[MAXN];           // gate logit
__device__ float    g_al[MAXN];           // a1 logit
__device__ float    g_e[MAXN];
__device__ float    g_xgA[MAXG * EMB];
__device__ float    g_xgB[MAXG * EMB];
__device__ int      g_deg[MAXN];          // zero at load; re-zeroed by k_scan
__device__ int      g_row[MAXN + 1];
__device__ int      g_cur[MAXN];
__device__ int      g_csr[MAXE];          // BYTE offsets (src*64) into g_mh
__device__ int      g_part[1024];
__device__ int      g_gs[MAXG + 1];
__device__ int      g_ctr;
__device__ int      g_rel;                // release flag for spin-scan

__device__ __forceinline__ float lrelu(float v) { return v > 0.f ? v : 0.01f * v; }

__device__ __forceinline__ __half2 hmax2s(__half2 a, int o) {
    unsigned u = __shfl_xor_sync(FULL, *(unsigned*)&a, o);
    return __hmax2(a, *(__half2*)&u);
}

// ---------------- setup: hist || pre || embed+msg0 (grid-partitioned) ----------------
__global__ __launch_bounds__(256) void k_setup(
        const float* __restrict__ nf, const float* __restrict__ We,
        const float* __restrict__ be, const float* __restrict__ Wm,
        const float* __restrict__ bm, const int* __restrict__ ei,
        const int* __restrict__ batch, int N, int E, int G, int eB, int nB, int mB) {
    int b = blockIdx.x;
    int tid = threadIdx.x;
    if (b < eB) {                       // ---- hist (deg starts zero) ----
        int e = b * 256 + tid;
        if (e < E) atomicAdd(&g_deg[ei[E + e]], 1);
        return;
    }
    b -= eB;
    if (b < nB) {                       // ---- pre: graph offsets, zeroing ----
        int n = b * 256 + tid;
        if (n == 0) { g_ctr = 0; g_rel = 0; g_row[N] = E; }
        if (n < G * EMB) { g_xgA[n] = 0.f; g_xgB[n] = 0.f; }
        if (n >= N) return;
        int bb = batch[n];
        int bp = (n == 0) ? -1 : batch[n - 1];
        for (int g = bp + 1; g <= bb; g++) g_gs[g] = n;
        if (n == N - 1) for (int g = bb + 1; g <= G; g++) g_gs[g] = N;
        return;
    }
    b -= nB;                            // ---- fused embed + msg0 ----
    int lane = tid & 31;
    float wE[32], bE[32], wm[32];
#pragma unroll
    for (int k = 0; k < 32; k++) { wE[k] = We[k]; bE[k] = be[k]; wm[k] = Wm[k * 32 + lane]; }
    float bmv = bm[lane];
    int warp = (b * 256 + tid) >> 5;
    int nwarps = mB * 8;
    for (int n = warp; n < N; n += nwarps) {
        float f = __ldg(&nf[n]);
        g_x[n * 32 + lane] = lrelu(f * wE[lane] + bE[lane]);
        float a0 = bmv, a1 = 0.f, a2 = 0.f, a3 = 0.f;
#pragma unroll
        for (int k = 0; k < 32; k += 4) {
            a0 += lrelu(f * wE[k + 0] + bE[k + 0]) * wm[k + 0];
            a1 += lrelu(f * wE[k + 1] + bE[k + 1]) * wm[k + 1];
            a2 += lrelu(f * wE[k + 2] + bE[k + 2]) * wm[k + 2];
            a3 += lrelu(f * wE[k + 3] + bE[k + 3]) * wm[k + 3];
        }
        g_mh[n * 32 + lane] = __float2half(lrelu((a0 + a1) + (a2 + a3)));
    }
}

// ---------------- single-pass scan with wide release ----------------
__global__ __launch_bounds__(512) void k_scan(int N, int nb) {
    __shared__ int sm[512];
    __shared__ int sp[512];
    __shared__ bool last;
    int t = threadIdx.x, b = blockIdx.x;
    int i = b * 512 + t;
    int v = (i < N) ? g_deg[i] : 0;
    sm[t] = v;
    __syncthreads();
    for (int off = 1; off < 512; off <<= 1) {      // inclusive local scan
        int a = (t >= off) ? sm[t - off] : 0;
        __syncthreads();
        sm[t] += a;
        __syncthreads();
    }
    if (t == 0) {
        g_part[b] = sm[511];
        __threadfence();
        int old = atomicAdd(&g_ctr, 1);
        last = (old == nb - 1);
    }
    __syncthreads();
    if (last) {
        int pv = (t < nb) ? g_part[t] : 0;
        sp[t] = pv;
        __syncthreads();
        for (int off = 1; off < 512; off <<= 1) {
            int a = (t >= off) ? sp[t - off] : 0;
            __syncthreads();
            sp[t] += a;
            __syncthreads();
        }
        if (t < nb) g_part[t] = sp[t] - pv;        // exclusive base per chunk
        __threadfence();
        if (t == 0) ((volatile int*)&g_rel)[0] = 1;
    } else {
        if (t == 0) {
            while (((volatile int*)&g_rel)[0] == 0) { }
        }
        __syncthreads();
        __threadfence();
    }
    int base = ((volatile int*)g_part)[b];
    if (i < N) {
        int r = base + sm[t] - v;                  // exclusive
        g_row[i] = r;
        g_cur[i] = r;
        g_deg[i] = 0;                              // ready for next replay
    }
}

__global__ void k_scatter(const int* __restrict__ ei, int E) {
    int e = blockIdx.x * blockDim.x + threadIdx.x;
    if (e >= E) return;
    int s = __ldg(&ei[e]);
    int d = __ldg(&ei[E + e]);
    int pos = atomicAdd(&g_cur[d], 1);
    g_csr[pos] = s << 6;          // byte offset into g_mh (64 B per node row)
}

// ---------------- fused gather-max + update MLP (software-pipelined) ----------------
// agg = max over in-edges of m[src] (fp16, in regs);
// x = lrelu([x, xg[batch], agg] @ Wa + ba) + x
// Node n+1's row/deg + first TWO rounds of CSR offsets are prefetched during
// node n's compute, so rounds 0-1 message loads issue with no CSR wait.
__global__ __launch_bounds__(128) void k_gathupd(const int* __restrict__ batch,
                                                 const float* __restrict__ Wa,
                                                 const float* __restrict__ ba,
                                                 int N, int cur) {
    __shared__ __align__(16) unsigned sagg[4][16];   // per-warp 64B agg row
    int lane = threadIdx.x & 31;
    int wid = threadIdx.x >> 5;
    float w[96];
#pragma unroll
    for (int k = 0; k < 96; k++) w[k] = Wa[k * 32 + lane];
    float bv = ba[lane];
    const float* xg = cur ? g_xgB : g_xgA;
    int eg = lane >> 2;            // edge slot 0..7
    int ch = lane & 3;             // 16B chunk 0..3 of the 64B message row
    const char* mbase = (const char*)g_mh + ch * 16;

    int warp = (blockIdx.x * blockDim.x + threadIdx.x) >> 5;
    int nwarps = (gridDim.x * blockDim.x) >> 5;
    int chunk = (N + nwarps - 1) / nwarps;
    int n0 = warp * chunk;
    int n1 = min(N, n0 + chunk);
    if (n0 >= n1) return;
    int gprev = -1;
    float xgacc = 0.f;

    // ---- prologue prefetch for node n0 ----
    int pbase = g_row[n0];
    int pdeg  = g_row[n0 + 1] - pbase;
    int poff0 = (eg < pdeg)      ? __ldg(&g_csr[pbase + eg])      : 0;
    int poff1 = (8 + eg < pdeg)  ? __ldg(&g_csr[pbase + 8 + eg])  : 0;

    for (int n = n0; n < n1; n++) {
        int base = pbase, deg = pdeg;
        int off0 = poff0, off1 = poff1;
        bool h0 = eg < deg, h1 = 8 + eg < deg;
        // rounds 0-1 message loads: CSR offsets already resident
        uint4 v0, v1;
        if (h0) v0 = *(const uint4*)(mbase + off0);
        if (h1) v1 = *(const uint4*)(mbase + off1);
        // prefetch next node (hidden under v0/v1 latency)
        if (n + 1 < n1) {
            pbase = g_row[n + 1];
            pdeg  = g_row[n + 2] - pbase;
            poff0 = (eg < pdeg)     ? __ldg(&g_csr[pbase + eg])     : 0;
            poff1 = (8 + eg < pdeg) ? __ldg(&g_csr[pbase + 8 + eg]) : 0;
        }
        // ---- gather-max (fp16) ----
        __half2 ninf = __float2half2_rn(-CUDART_INF_F);
        __half2 m0 = ninf, m1 = ninf, m2 = ninf, m3 = ninf;
        if (h0) {
            m0 = __hmax2(m0, *(__half2*)&v0.x);
            m1 = __hmax2(m1, *(__half2*)&v0.y);
            m2 = __hmax2(m2, *(__half2*)&v0.z);
            m3 = __hmax2(m3, *(__half2*)&v0.w);
        }
        if (h1) {
            m0 = __hmax2(m0, *(__half2*)&v1.x);
            m1 = __hmax2(m1, *(__half2*)&v1.y);
            m2 = __hmax2(m2, *(__half2*)&v1.z);
            m3 = __hmax2(m3, *(__half2*)&v1.w);
        }
        for (int j = 16 + eg; j < deg; j += 8) {     // residual rounds (deg>16)
            int off = __ldg(&g_csr[base + j]);
            uint4 v = *(const uint4*)(mbase + off);
            m0 = __hmax2(m0, *(__half2*)&v.x);
            m1 = __hmax2(m1, *(__half2*)&v.y);
            m2 = __hmax2(m2, *(__half2*)&v.z);
            m3 = __hmax2(m3, *(__half2*)&v.w);
        }
#pragma unroll
        for (int o = 4; o <= 16; o <<= 1) {
            m0 = hmax2s(m0, o); m1 = hmax2s(m1, o);
            m2 = hmax2s(m2, o); m3 = hmax2s(m3, o);
        }
        if (deg == 0) {
            __half2 z = __float2half2_rn(0.f);
            m0 = z; m1 = z; m2 = z; m3 = z;
        }
        // ---- stage agg row in shared (lanes 0..3 hold chunks 0..3) ----
        __syncwarp();
        if (lane < 4) {
            uint4 r;
            r.x = *(unsigned*)&m0; r.y = *(unsigned*)&m1;
            r.z = *(unsigned*)&m2; r.w = *(unsigned*)&m3;
            *(uint4*)&sagg[wid][lane * 4] = r;
        }
        __syncwarp();
        // ---- xg term (hoisted per graph; batch sorted) ----
        int gidx = __ldg(&batch[n]);
        if (gidx != gprev) {
            gprev = gidx;
            const float4* xgr = (const float4*)(xg + gidx * 32);
            float b0 = 0.f, b1 = 0.f, b2 = 0.f, b3 = 0.f;
#pragma unroll
            for (int c = 0; c < 8; c++) {
                float4 v = xgr[c];
                b0 += v.x * w[32 + c * 4 + 0];
                b1 += v.y * w[32 + c * 4 + 1];
                b2 += v.z * w[32 + c * 4 + 2];
                b3 += v.w * w[32 + c * 4 + 3];
            }
            xgacc = (b0 + b1) + (b2 + b3);
        }
        // ---- x block ----
        const float4* xr = (const float4*)(g_x + n * 32);
        float a0 = bv + xgacc, a1 = 0.f, a2 = 0.f, a3 = 0.f;
#pragma unroll
        for (int c = 0; c < 8; c++) {
            float4 v = xr[c];
            a0 += v.x * w[c * 4 + 0];
            a1 += v.y * w[c * 4 + 1];
            a2 += v.z * w[c * 4 + 2];
            a3 += v.w * w[c * 4 + 3];
        }
        float xv = g_x[n * 32 + lane];
        // ---- agg block: broadcast-read the staged row ----
#pragma unroll
        for (int c2 = 0; c2 < 4; c2++) {
            uint4 u = *(const uint4*)&sagg[wid][c2 * 4];
            float2 f0 = __half22float2(*(__half2*)&u.x);
            float2 f1 = __half22float2(*(__half2*)&u.y);
            float2 f2 = __half22float2(*(__half2*)&u.z);
            float2 f3 = __half22float2(*(__half2*)&u.w);
            a0 += f0.x * w[64 + c2 * 8 + 0];
            a1 += f0.y * w[64 + c2 * 8 + 1];
            a2 += f1.x * w[64 + c2 * 8 + 2];
            a3 += f1.y * w[64 + c2 * 8 + 3];
            a0 += f2.x * w[64 + c2 * 8 + 4];
            a1 += f2.y * w[64 + c2 * 8 + 5];
            a2 += f3.x * w[64 + c2 * 8 + 6];
            a3 += f3.y * w[64 + c2 * 8 + 7];
        }
        g_x[n * 32 + lane] = lrelu((a0 + a1) + (a2 + a3)) + xv;
    }
}

// fused: feat = lrelu(x@Wf+bf); gate logit; next-step msg (fp16); optional a1 logit
__global__ __launch_bounds__(128) void k_featmsg(const float* __restrict__ Wg,
                                                 const float* __restrict__ bg,
                                                 const float* __restrict__ Wf,
                                                 const float* __restrict__ bf,
                                                 const float* __restrict__ Wm,
                                                 const float* __restrict__ bm,
                                                 const float* __restrict__ Wa1,
                                                 const float* __restrict__ ba1,
                                                 int N, int do_msg, int do_a1) {
    int lane = threadIdx.x & 31;
    int ch = lane & 7;
    float wf[32], wm[32], wg4[4], wa4[4];
#pragma unroll
    for (int k = 0; k < 32; k++) {
        wf[k] = Wf[k * 32 + lane];
        wm[k] = do_msg ? Wm[k * 32 + lane] : 0.f;
    }
#pragma unroll
    for (int k = 0; k < 4; k++) {
        wg4[k] = Wg[ch * 4 + k];
        wa4[k] = do_a1 ? Wa1[ch * 4 + k] : 0.f;
    }
    float bfv = bf[lane];
    float bmv = do_msg ? bm[lane] : 0.f;
    float bgv = bg[0];
    float ba1v = do_a1 ? ba1[0] : 0.f;
    int warp = (blockIdx.x * blockDim.x + threadIdx.x) >> 5;
    int nwarps = (gridDim.x * blockDim.x) >> 5;
    for (int n = warp; n < N; n += nwarps) {
        const float4* xr = (const float4*)(g_x + n * 32);
        float a0 = bfv, a1 = 0.f, a2 = 0.f, a3 = 0.f;
        float q0 = bmv, q1 = 0.f, q2 = 0.f, q3 = 0.f;
        float p = 0.f, pa = 0.f;
#pragma unroll
        for (int c = 0; c < 8; c++) {
            float4 v = xr[c];
            a0 += v.x * wf[c * 4 + 0];
            a1 += v.y * wf[c * 4 + 1];
            a2 += v.z * wf[c * 4 + 2];
            a3 += v.w * wf[c * 4 + 3];
            if (do_msg) {
                q0 += v.x * wm[c * 4 + 0];
                q1 += v.y * wm[c * 4 + 1];
                q2 += v.z * wm[c * 4 + 2];
                q3 += v.w * wm[c * 4 + 3];
            }
            if (c == ch) {
                p  = v.x * wg4[0] + v.y * wg4[1] + v.z * wg4[2] + v.w * wg4[3];
                if (do_a1)
                    pa = v.x * wa4[0] + v.y * wa4[1] + v.z * wa4[2] + v.w * wa4[3];
            }
        }
        g_feat[n * 32 + lane] = lrelu((a0 + a1) + (a2 + a3));
        if (do_msg)
            g_mh[n * 32 + lane] = __float2half(lrelu((q0 + q1) + (q2 + q3)));
#pragma unroll
        for (int o = 1; o <= 4; o <<= 1) {
            p += __shfl_xor_sync(FULL, p, o);
            if (do_a1) pa += __shfl_xor_sync(FULL, pa, o);
        }
        if (lane == 0) {
            g_gl[n] = p + bgv;
            if (do_a1) g_al[n] = pa + ba1v;
        }
    }
}

// block-per-graph: segment softmax over gate logits + attention pooling + transform
__global__ void k_pooltrans(const float* __restrict__ Wt, const float* __restrict__ bt,
                            int cur) {
    __shared__ float sred[16];
    __shared__ float sfac[16][32];
    __shared__ float smx, sinv;
    __shared__ float spooled[32];
    __shared__ float sxg[32];
    int g = blockIdx.x;
    int tid = threadIdx.x;
    int wid = tid >> 5, lane = tid & 31;
    int s = g_gs[g], e2 = g_gs[g + 1];

    float lmax = -CUDART_INF_F;
    for (int n = s + tid; n < e2; n += 512) lmax = fmaxf(lmax, g_gl[n]);
#pragma unroll
    for (int o = 16; o; o >>= 1) lmax = fmaxf(lmax, __shfl_xor_sync(FULL, lmax, o));
    if (lane == 0) sred[wid] = lmax;
    __syncthreads();
    if (tid == 0) {
        float m = sred[0];
#pragma unroll
        for (int w = 1; w < 16; w++) m = fmaxf(m, sred[w]);
        smx = m;
    }
    __syncthreads();
    float mx = smx;

    float facc = 0.f, se = 0.f;
    for (int n = s + wid; n < e2; n += 16) {
        float ev = __expf(g_gl[n] - mx);
        facc += ev * g_feat[n * 32 + lane];
        if (lane == 0) se += ev;
    }
    sfac[wid][lane] = facc;
    if (lane == 0) sred[wid] = se;
    __syncthreads();
    if (wid == 0) {
        float p = 0.f;
#pragma unroll
        for (int w = 0; w < 16; w++) p += sfac[w][lane];
        spooled[lane] = p;
        if (lane == 0) {
            float t = 0.f;
#pragma unroll
            for (int w = 0; w < 16; w++) t += sred[w];
            sinv = t > 0.f ? 1.f / t : 0.f;
        }
        const float* xgc = cur ? g_xgB : g_xgA;
        sxg[lane] = xgc[g * 32 + lane];
    }
    __syncthreads();

    if (tid < 32) {
        int c = tid;
        float inv = sinv;
        float acc = bt[c];
#pragma unroll
        for (int k = 0; k < 32; k++) acc += (spooled[k] * inv) * Wt[k * 32 + c];
#pragma unroll
        for (int k = 0; k < 32; k++) acc += sxg[k] * Wt[(32 + k) * 32 + c];
        float* xgn = cur ? g_xgA : g_xgB;
        xgn[g * 32 + c] = lrelu(acc) + sxg[c];
    }
}

__global__ void k_headsg(const float* __restrict__ Wv, const float* __restrict__ bv,
                         const float* __restrict__ Wa0, const float* __restrict__ ba0,
                         int G, int cur, float* __restrict__ out) {
    int g = blockIdx.x * blockDim.x + threadIdx.x;
    if (g >= G) return;
    const float* xg = cur ? g_xgB : g_xgA;
    float v = bv[0], l0 = ba0[0], l1 = ba0[1];
#pragma unroll
    for (int k = 0; k < 32; k++) {
        float xx = xg[g * 32 + k];
        v += xx * Wv[k];
        l0 += xx * Wa0[k * 2];
        l1 += xx * Wa0[k * 2 + 1];
    }
    out[g] = v;
    float mxv = fmaxf(l0, l1);
    float e0 = __expf(l0 - mxv), e1 = __expf(l1 - mxv);
    float ssum = e0 + e1;
    out[G + g * 2] = e0 / ssum;
    out[G + g * 2 + 1] = e1 / ssum;
}

// final a1 segment softmax over precomputed logits g_al
__global__ void k_a1(int G, float* __restrict__ out) {
    __shared__ float sred[8];
    __shared__ float smx, sinv;
    int g = blockIdx.x;
    int tid = threadIdx.x;
    int wid = tid >> 5, lane = tid & 31;
    int s = g_gs[g], e2 = g_gs[g + 1];

    float lmax = -CUDART_INF_F;
    for (int n = s + tid; n < e2; n += 256) lmax = fmaxf(lmax, g_al[n]);
#pragma unroll
    for (int o = 16; o; o >>= 1) lmax = fmaxf(lmax, __shfl_xor_sync(FULL, lmax, o));
    if (lane == 0) sred[wid] = lmax;
    __syncthreads();
    if (tid == 0) {
        float m = sred[0];
#pragma unroll
        for (int w = 1; w < 8; w++) m = fmaxf(m, sred[w]);
        smx = m;
    }
    __syncthreads();
    float mx = smx;

    float ps = 0.f;
    for (int n = s + tid; n < e2; n += 256) {
        float ev = __expf(g_al[n] - mx);
        g_e[n] = ev;
        ps += ev;
    }
#pragma unroll
    for (int o = 16; o; o >>= 1) ps += __shfl_xor_sync(FULL, ps, o);
    if (lane == 0) sred[wid] = ps;
    __syncthreads();
    if (tid == 0) {
        float t = 0.f;
#pragma unroll
        for (int w = 0; w < 8; w++) t += sred[w];
        sinv = t > 0.f ? 1.f / t : 0.f;
    }
    __syncthreads();
    float inv = sinv;
    for (int n = s + tid; n < e2; n += 256)
        out[3 * G + n] = g_e[n] * inv;
}

// ---------------- launcher ----------------
extern "C" void kernel_launch(void* const* d_in, const int* in_sizes, int n_in,
                              void* d_out, int out_size) {
    const float* nf   = (const float*)d_in[0];
    const int*   ei   = (const int*)d_in[1];
    const int*   batch= (const int*)d_in[2];
    const float* We   = (const float*)d_in[4];
    const float* be   = (const float*)d_in[5];
    const float* Wm   = (const float*)d_in[6];
    const float* bm   = (const float*)d_in[7];
    const float* Wa   = (const float*)d_in[8];
    const float* ba   = (const float*)d_in[9];
    const float* Wg   = (const float*)d_in[10];
    const float* bg   = (const float*)d_in[11];
    const float* Wf   = (const float*)d_in[12];
    const float* bf   = (const float*)d_in[13];
    const float* Wt   = (const float*)d_in[14];
    const float* bt   = (const float*)d_in[15];
    const float* Wv   = (const float*)d_in[16];
    const float* bv   = (const float*)d_in[17];
    const float* Wa0  = (const float*)d_in[18];
    const float* ba0  = (const float*)d_in[19];
    const float* Wa1  = (const float*)d_in[20];
    const float* ba1  = (const float*)d_in[21];
    float* out = (float*)d_out;

    int N = in_sizes[0];
    int E = in_sizes[1] / 2;
    int G = (out_size - N) / 3;
    int S = in_sizes[6] / (EMB * EMB);

    int eB   = (E + 255) / 256;
    int nB   = (N + 255) / 256;
    int mB   = 296;
    int nsb  = (N + 511) / 512;

    k_setup<<<eB + nB + mB, 256>>>(nf, We, be, Wm, bm, ei, batch, N, E, G, eB, nB, mB);
    k_scan<<<nsb, 512>>>(N, nsb);
    k_scatter<<<eB, 256>>>(ei, E);

    int cur = 0;
    for (int i = 0; i < S; i++) {
        int lastS = (i == S - 1);
        k_gathupd<<<444, 128>>>(batch, Wa + i * 96 * 32, ba + i * 32, N, cur);  // launch #4 on i=0
        k_featmsg<<<740, 128>>>(Wg + i * 32, bg + i, Wf + i * 1024, bf + i * 32,
                                Wm + (lastS ? 0 : (i + 1) * 1024),
                                bm + (lastS ? 0 : (i + 1) * 32),
                                Wa1, ba1, N, lastS ? 0 : 1, lastS ? 1 : 0);
        k_pooltrans<<<G, 512>>>(Wt + i * 64 * 32, bt + i * 32, cur);
        cur ^= 1;
    }

    k_headsg<<<(G + 127) / 128, 128>>>(Wv, bv, Wa0, ba0, G, cur, out);
    k_a1<<<G, 256>>>(G, out);
}

// round 16
// speedup vs baseline: 1.5645x; 1.1728x over previous
#include <cuda_runtime.h>
#include <cuda_fp16.h>
#include <math_constants.h>

#define EMB 32
#define MAXN 200704
#define MAXE 3201024
#define MAXG 512
#define FULL 0xffffffffu

// ---------------- scratch ----------------
__device__ float    g_x[MAXN * EMB];
__device__ __align__(16) __half g_mh[MAXN * EMB];    // messages (fp16)
__device__ __align__(16) __half g_aggh[MAXN * EMB];  // gather-max result (fp16)
__device__ float    g_feat[MAXN * EMB];
__device__ float    g_gl[MAXN];           // gate logit
__device__ float    g_al[MAXN];           // a1 logit
__device__ float    g_e[MAXN];
__device__ float    g_xgA[MAXG * EMB];
__device__ float    g_xgB[MAXG * EMB];
__device__ float    g_xgdot[MAXG * EMB];  // per-graph xg @ Wa[32:64] (next step)
__device__ int      g_deg[MAXN];          // zero at load; re-zeroed by k_scan
__device__ int      g_row[MAXN + 1];
__device__ int      g_cur[MAXN];
__device__ int      g_csr[MAXE];          // BYTE offsets (src*64) into g_mh
__device__ int      g_part[1024];
__device__ int      g_gs[MAXG + 1];
__device__ int      g_ctr;
__device__ int      g_rel;                // release flag for spin-scan

__device__ __forceinline__ float lrelu(float v) { return v > 0.f ? v : 0.01f * v; }

__device__ __forceinline__ __half2 hmax2s(__half2 a, int o) {
    unsigned u = __shfl_xor_sync(FULL, *(unsigned*)&a, o);
    return __hmax2(a, *(__half2*)&u);
}

// ---------------- setup: hist || pre || embed+msg0 (grid-partitioned) ----------------
__global__ __launch_bounds__(256) void k_setup(
        const float* __restrict__ nf, const float* __restrict__ We,
        const float* __restrict__ be, const float* __restrict__ Wm,
        const float* __restrict__ bm, const int* __restrict__ ei,
        const int* __restrict__ batch, int N, int E, int G, int eB, int nB, int mB) {
    int b = blockIdx.x;
    int tid = threadIdx.x;
    if (b < eB) {                       // ---- hist (deg starts zero) ----
        int e = b * 256 + tid;
        if (e < E) atomicAdd(&g_deg[ei[E + e]], 1);
        return;
    }
    b -= eB;
    if (b < nB) {                       // ---- pre: graph offsets, zeroing ----
        int n = b * 256 + tid;
        if (n == 0) { g_ctr = 0; g_rel = 0; g_row[N] = E; }
        if (n < G * EMB) { g_xgA[n] = 0.f; g_xgB[n] = 0.f; g_xgdot[n] = 0.f; }
        if (n >= N) return;
        int bb = batch[n];
        int bp = (n == 0) ? -1 : batch[n - 1];
        for (int g = bp + 1; g <= bb; g++) g_gs[g] = n;
        if (n == N - 1) for (int g = bb + 1; g <= G; g++) g_gs[g] = N;
        return;
    }
    b -= nB;                            // ---- fused embed + msg0 ----
    int lane = tid & 31;
    float wE[32], bE[32], wm[32];
#pragma unroll
    for (int k = 0; k < 32; k++) { wE[k] = We[k]; bE[k] = be[k]; wm[k] = Wm[k * 32 + lane]; }
    float bmv = bm[lane];
    int warp = (b * 256 + tid) >> 5;
    int nwarps = mB * 8;
    for (int n = warp; n < N; n += nwarps) {
        float f = __ldg(&nf[n]);
        g_x[n * 32 + lane] = lrelu(f * wE[lane] + bE[lane]);
        float a0 = bmv, a1 = 0.f, a2 = 0.f, a3 = 0.f;
#pragma unroll
        for (int k = 0; k < 32; k += 4) {
            a0 += lrelu(f * wE[k + 0] + bE[k + 0]) * wm[k + 0];
            a1 += lrelu(f * wE[k + 1] + bE[k + 1]) * wm[k + 1];
            a2 += lrelu(f * wE[k + 2] + bE[k + 2]) * wm[k + 2];
            a3 += lrelu(f * wE[k + 3] + bE[k + 3]) * wm[k + 3];
        }
        g_mh[n * 32 + lane] = __float2half(lrelu((a0 + a1) + (a2 + a3)));
    }
}

// ---------------- single-pass scan with wide release ----------------
__global__ __launch_bounds__(512) void k_scan(int N, int nb) {
    __shared__ int sm[512];
    __shared__ int sp[512];
    __shared__ bool last;
    int t = threadIdx.x, b = blockIdx.x;
    int i = b * 512 + t;
    int v = (i < N) ? g_deg[i] : 0;
    sm[t] = v;
    __syncthreads();
    for (int off = 1; off < 512; off <<= 1) {
        int a = (t >= off) ? sm[t - off] : 0;
        __syncthreads();
        sm[t] += a;
        __syncthreads();
    }
    if (t == 0) {
        g_part[b] = sm[511];
        __threadfence();
        int old = atomicAdd(&g_ctr, 1);
        last = (old == nb - 1);
    }
    __syncthreads();
    if (last) {
        int pv = (t < nb) ? g_part[t] : 0;
        sp[t] = pv;
        __syncthreads();
        for (int off = 1; off < 512; off <<= 1) {
            int a = (t >= off) ? sp[t - off] : 0;
            __syncthreads();
            sp[t] += a;
            __syncthreads();
        }
        if (t < nb) g_part[t] = sp[t] - pv;
        __threadfence();
        if (t == 0) ((volatile int*)&g_rel)[0] = 1;
    } else {
        if (t == 0) {
            while (((volatile int*)&g_rel)[0] == 0) { }
        }
        __syncthreads();
        __threadfence();
    }
    int base = ((volatile int*)g_part)[b];
    if (i < N) {
        int r = base + sm[t] - v;
        g_row[i] = r;
        g_cur[i] = r;
        g_deg[i] = 0;
    }
}

__global__ void k_scatter(const int* __restrict__ ei, int E) {
    int e = blockIdx.x * blockDim.x + threadIdx.x;
    if (e >= E) return;
    int s = __ldg(&ei[e]);
    int d = __ldg(&ei[E + e]);
    int pos = atomicAdd(&g_cur[d], 1);
    g_csr[pos] = s << 6;          // byte offset into g_mh (64 B per node row)
}

// ---------------- gather-max (standalone, high occupancy) ----------------
// warp per node; lane = edge-slot(0..7) x 16B-chunk(0..3); fp16 maxima
__global__ void k_gather(int N) {
    int t = blockIdx.x * blockDim.x + threadIdx.x;
    int n = t >> 5;
    if (n >= N) return;
    int lane = t & 31;
    int eg = lane >> 2;
    int ch = lane & 3;
    const char* mbase = (const char*)g_mh + ch * 16;
    int base = g_row[n];
    int deg = g_row[n + 1] - base;
    __half2 ninf = __float2half2_rn(-CUDART_INF_F);
    __half2 m0 = ninf, m1 = ninf, m2 = ninf, m3 = ninf;
    for (int j0 = 0; j0 < deg; j0 += 8) {
        int j = j0 + eg;
        if (j < deg) {
            int off = __ldg(&g_csr[base + j]);
            uint4 v = *(const uint4*)(mbase + off);
            m0 = __hmax2(m0, *(__half2*)&v.x);
            m1 = __hmax2(m1, *(__half2*)&v.y);
            m2 = __hmax2(m2, *(__half2*)&v.z);
            m3 = __hmax2(m3, *(__half2*)&v.w);
        }
    }
#pragma unroll
    for (int o = 4; o <= 16; o <<= 1) {
        m0 = hmax2s(m0, o); m1 = hmax2s(m1, o);
        m2 = hmax2s(m2, o); m3 = hmax2s(m3, o);
    }
    if (eg == 0) {
        uint4 r;
        if (deg > 0) {
            r.x = *(unsigned*)&m0; r.y = *(unsigned*)&m1;
            r.z = *(unsigned*)&m2; r.w = *(unsigned*)&m3;
        } else {
            r.x = r.y = r.z = r.w = 0u;
        }
        *(uint4*)(g_aggh + n * 32 + ch * 8) = r;
    }
}

// ---------------- update MLP (lean: w[64] + precomputed xgdot) ----------------
// x = lrelu(x@Wa[0:32] + agg@Wa[64:96] + xgdot[batch] + ba) + x
__global__ __launch_bounds__(128) void k_upd(const int* __restrict__ batch,
                                             const float* __restrict__ Wa,
                                             const float* __restrict__ ba,
                                             int N) {
    int lane = threadIdx.x & 31;
    float w[64];
#pragma unroll
    for (int k = 0; k < 32; k++) w[k] = Wa[k * 32 + lane];             // x rows
#pragma unroll
    for (int k = 0; k < 32; k++) w[32 + k] = Wa[(64 + k) * 32 + lane]; // agg rows
    float bv = ba[lane];
    int warp = (blockIdx.x * blockDim.x + threadIdx.x) >> 5;
    int nwarps = (gridDim.x * blockDim.x) >> 5;
    for (int n = warp; n < N; n += nwarps) {
        int gidx = __ldg(&batch[n]);
        float a0 = bv + __ldg(&g_xgdot[gidx * 32 + lane]);
        float a1 = 0.f, a2 = 0.f, a3 = 0.f;
        const float4* xr = (const float4*)(g_x + n * 32);
        const uint4* ar = (const uint4*)(g_aggh + n * 32);
#pragma unroll
        for (int c = 0; c < 8; c++) {
            float4 v = xr[c];
            a0 += v.x * w[c * 4 + 0];
            a1 += v.y * w[c * 4 + 1];
            a2 += v.z * w[c * 4 + 2];
            a3 += v.w * w[c * 4 + 3];
        }
#pragma unroll
        for (int c = 0; c < 4; c++) {
            uint4 u = ar[c];
            float2 f0 = __half22float2(*(__half2*)&u.x);
            float2 f1 = __half22float2(*(__half2*)&u.y);
            float2 f2 = __half22float2(*(__half2*)&u.z);
            float2 f3 = __half22float2(*(__half2*)&u.w);
            a0 += f0.x * w[32 + c * 8 + 0];
            a1 += f0.y * w[32 + c * 8 + 1];
            a2 += f1.x * w[32 + c * 8 + 2];
            a3 += f1.y * w[32 + c * 8 + 3];
            a0 += f2.x * w[32 + c * 8 + 4];
            a1 += f2.y * w[32 + c * 8 + 5];
            a2 += f3.x * w[32 + c * 8 + 6];
            a3 += f3.y * w[32 + c * 8 + 7];
        }
        float xv = g_x[n * 32 + lane];
        g_x[n * 32 + lane] = lrelu((a0 + a1) + (a2 + a3)) + xv;
    }
}

// fused: feat = lrelu(x@Wf+bf); gate logit; next-step msg (fp16); optional a1 logit
__global__ __launch_bounds__(128) void k_featmsg(const float* __restrict__ Wg,
                                                 const float* __restrict__ bg,
                                                 const float* __restrict__ Wf,
                                                 const float* __restrict__ bf,
                                                 const float* __restrict__ Wm,
                                                 const float* __restrict__ bm,
                                                 const float* __restrict__ Wa1,
                                                 const float* __restrict__ ba1,
                                                 int N, int do_msg, int do_a1) {
    int lane = threadIdx.x & 31;
    int ch = lane & 7;
    float wf[32], wm[32], wg4[4], wa4[4];
#pragma unroll
    for (int k = 0; k < 32; k++) {
        wf[k] = Wf[k * 32 + lane];
        wm[k] = do_msg ? Wm[k * 32 + lane] : 0.f;
    }
#pragma unroll
    for (int k = 0; k < 4; k++) {
        wg4[k] = Wg[ch * 4 + k];
        wa4[k] = do_a1 ? Wa1[ch * 4 + k] : 0.f;
    }
    float bfv = bf[lane];
    float bmv = do_msg ? bm[lane] : 0.f;
    float bgv = bg[0];
    float ba1v = do_a1 ? ba1[0] : 0.f;
    int warp = (blockIdx.x * blockDim.x + threadIdx.x) >> 5;
    int nwarps = (gridDim.x * blockDim.x) >> 5;
    for (int n = warp; n < N; n += nwarps) {
        const float4* xr = (const float4*)(g_x + n * 32);
        float a0 = bfv, a1 = 0.f, a2 = 0.f, a3 = 0.f;
        float q0 = bmv, q1 = 0.f, q2 = 0.f, q3 = 0.f;
        float p = 0.f, pa = 0.f;
#pragma unroll
        for (int c = 0; c < 8; c++) {
            float4 v = xr[c];
            a0 += v.x * wf[c * 4 + 0];
            a1 += v.y * wf[c * 4 + 1];
            a2 += v.z * wf[c * 4 + 2];
            a3 += v.w * wf[c * 4 + 3];
            if (do_msg) {
                q0 += v.x * wm[c * 4 + 0];
                q1 += v.y * wm[c * 4 + 1];
                q2 += v.z * wm[c * 4 + 2];
                q3 += v.w * wm[c * 4 + 3];
            }
            if (c == ch) {
                p  = v.x * wg4[0] + v.y * wg4[1] + v.z * wg4[2] + v.w * wg4[3];
                if (do_a1)
                    pa = v.x * wa4[0] + v.y * wa4[1] + v.z * wa4[2] + v.w * wa4[3];
            }
        }
        g_feat[n * 32 + lane] = lrelu((a0 + a1) + (a2 + a3));
        if (do_msg)
            g_mh[n * 32 + lane] = __float2half(lrelu((q0 + q1) + (q2 + q3)));
#pragma unroll
        for (int o = 1; o <= 4; o <<= 1) {
            p += __shfl_xor_sync(FULL, p, o);
            if (do_a1) pa += __shfl_xor_sync(FULL, pa, o);
        }
        if (lane == 0) {
            g_gl[n] = p + bgv;
            if (do_a1) g_al[n] = pa + ba1v;
        }
    }
}

// block-per-graph: segment softmax + attention pooling + transform;
// also precomputes g_xgdot for the NEXT step's update MLP.
__global__ void k_pooltrans(const float* __restrict__ Wt, const float* __restrict__ bt,
                            const float* __restrict__ WaN, int do_next, int cur) {
    __shared__ float sred[16];
    __shared__ float sfac[16][32];
    __shared__ float smx, sinv;
    __shared__ float spooled[32];
    __shared__ float sxg[32];
    __shared__ float sxgn[32];
    int g = blockIdx.x;
    int tid = threadIdx.x;
    int wid = tid >> 5, lane = tid & 31;
    int s = g_gs[g], e2 = g_gs[g + 1];

    float lmax = -CUDART_INF_F;
    for (int n = s + tid; n < e2; n += 512) lmax = fmaxf(lmax, g_gl[n]);
#pragma unroll
    for (int o = 16; o; o >>= 1) lmax = fmaxf(lmax, __shfl_xor_sync(FULL, lmax, o));
    if (lane == 0) sred[wid] = lmax;
    __syncthreads();
    if (tid == 0) {
        float m = sred[0];
#pragma unroll
        for (int w = 1; w < 16; w++) m = fmaxf(m, sred[w]);
        smx = m;
    }
    __syncthreads();
    float mx = smx;

    float facc = 0.f, se = 0.f;
    for (int n = s + wid; n < e2; n += 16) {
        float ev = __expf(g_gl[n] - mx);
        facc += ev * g_feat[n * 32 + lane];
        if (lane == 0) se += ev;
    }
    sfac[wid][lane] = facc;
    if (lane == 0) sred[wid] = se;
    __syncthreads();
    if (wid == 0) {
        float p = 0.f;
#pragma unroll
        for (int w = 0; w < 16; w++) p += sfac[w][lane];
        spooled[lane] = p;
        if (lane == 0) {
            float t = 0.f;
#pragma unroll
            for (int w = 0; w < 16; w++) t += sred[w];
            sinv = t > 0.f ? 1.f / t : 0.f;
        }
        const float* xgc = cur ? g_xgB : g_xgA;
        sxg[lane] = xgc[g * 32 + lane];
    }
    __syncthreads();

    if (tid < 32) {
        int c = tid;
        float inv = sinv;
        float acc = bt[c];
#pragma unroll
        for (int k = 0; k < 32; k++) acc += (spooled[k] * inv) * Wt[k * 32 + c];
#pragma unroll
        for (int k = 0; k < 32; k++) acc += sxg[k] * Wt[(32 + k) * 32 + c];
        float* xgn = cur ? g_xgA : g_xgB;
        float xnew = lrelu(acc) + sxg[c];
        xgn[g * 32 + c] = xnew;
        sxgn[c] = xnew;
        __syncwarp();
        if (do_next) {      // xgdot[c] = sum_k xg_next[k] * WaN[(32+k)*32+c]
            float d0 = 0.f, d1 = 0.f, d2 = 0.f, d3 = 0.f;
#pragma unroll
            for (int k = 0; k < 32; k += 4) {
                d0 += sxgn[k + 0] * __ldg(&WaN[(32 + k + 0) * 32 + c]);
                d1 += sxgn[k + 1] * __ldg(&WaN[(32 + k + 1) * 32 + c]);
                d2 += sxgn[k + 2] * __ldg(&WaN[(32 + k + 2) * 32 + c]);
                d3 += sxgn[k + 3] * __ldg(&WaN[(32 + k + 3) * 32 + c]);
            }
            g_xgdot[g * 32 + c] = (d0 + d1) + (d2 + d3);
        }
    }
}

__global__ void k_headsg(const float* __restrict__ Wv, const float* __restrict__ bv,
                         const float* __restrict__ Wa0, const float* __restrict__ ba0,
                         int G, int cur, float* __restrict__ out) {
    int g = blockIdx.x * blockDim.x + threadIdx.x;
    if (g >= G) return;
    const float* xg = cur ? g_xgB : g_xgA;
    float v = bv[0], l0 = ba0[0], l1 = ba0[1];
#pragma unroll
    for (int k = 0; k < 32; k++) {
        float xx = xg[g * 32 + k];
        v += xx * Wv[k];
        l0 += xx * Wa0[k * 2];
        l1 += xx * Wa0[k * 2 + 1];
    }
    out[g] = v;
    float mxv = fmaxf(l0, l1);
    float e0 = __expf(l0 - mxv), e1 = __expf(l1 - mxv);
    float ssum = e0 + e1;
    out[G + g * 2] = e0 / ssum;
    out[G + g * 2 + 1] = e1 / ssum;
}

// final a1 segment softmax over precomputed logits g_al
__global__ void k_a1(int G, float* __restrict__ out) {
    __shared__ float sred[8];
    __shared__ float smx, sinv;
    int g = blockIdx.x;
    int tid = threadIdx.x;
    int wid = tid >> 5, lane = tid & 31;
    int s = g_gs[g], e2 = g_gs[g + 1];

    float lmax = -CUDART_INF_F;
    for (int n = s + tid; n < e2; n += 256) lmax = fmaxf(lmax, g_al[n]);
#pragma unroll
    for (int o = 16; o; o >>= 1) lmax = fmaxf(lmax, __shfl_xor_sync(FULL, lmax, o));
    if (lane == 0) sred[wid] = lmax;
    __syncthreads();
    if (tid == 0) {
        float m = sred[0];
#pragma unroll
        for (int w = 1; w < 8; w++) m = fmaxf(m, sred[w]);
        smx = m;
    }
    __syncthreads();
    float mx = smx;

    float ps = 0.f;
    for (int n = s + tid; n < e2; n += 256) {
        float ev = __expf(g_al[n] - mx);
        g_e[n] = ev;
        ps += ev;
    }
#pragma unroll
    for (int o = 16; o; o >>= 1) ps += __shfl_xor_sync(FULL, ps, o);
    if (lane == 0) sred[wid] = ps;
    __syncthreads();
    if (tid == 0) {
        float t = 0.f;
#pragma unroll
        for (int w = 0; w < 8; w++) t += sred[w];
        sinv = t > 0.f ? 1.f / t : 0.f;
    }
    __syncthreads();
    float inv = sinv;
    for (int n = s + tid; n < e2; n += 256)
        out[3 * G + n] = g_e[n] * inv;
}

// ---------------- launcher ----------------
extern "C" void kernel_launch(void* const* d_in, const int* in_sizes, int n_in,
                              void* d_out, int out_size) {
    const float* nf   = (const float*)d_in[0];
    const int*   ei   = (const int*)d_in[1];
    const int*   batch= (const int*)d_in[2];
    const float* We   = (const float*)d_in[4];
    const float* be   = (const float*)d_in[5];
    const float* Wm   = (const float*)d_in[6];
    const float* bm   = (const float*)d_in[7];
    const float* Wa   = (const float*)d_in[8];
    const float* ba   = (const float*)d_in[9];
    const float* Wg   = (const float*)d_in[10];
    const float* bg   = (const float*)d_in[11];
    const float* Wf   = (const float*)d_in[12];
    const float* bf   = (const float*)d_in[13];
    const float* Wt   = (const float*)d_in[14];
    const float* bt   = (const float*)d_in[15];
    const float* Wv   = (const float*)d_in[16];
    const float* bv   = (const float*)d_in[17];
    const float* Wa0  = (const float*)d_in[18];
    const float* ba0  = (const float*)d_in[19];
    const float* Wa1  = (const float*)d_in[20];
    const float* ba1  = (const float*)d_in[21];
    float* out = (float*)d_out;

    int N = in_sizes[0];
    int E = in_sizes[1] / 2;
    int G = (out_size - N) / 3;
    int S = in_sizes[6] / (EMB * EMB);

    int eB   = (E + 255) / 256;
    int nB   = (N + 255) / 256;
    int nwB  = (N * 32 + 255) / 256;
    int mB   = 296;
    int nsb  = (N + 511) / 512;

    k_setup<<<eB + nB + mB, 256>>>(nf, We, be, Wm, bm, ei, batch, N, E, G, eB, nB, mB);
    k_scan<<<nsb, 512>>>(N, nsb);
    k_scatter<<<eB, 256>>>(ei, E);

    int cur = 0;
    for (int i = 0; i < S; i++) {
        int lastS = (i == S - 1);
        k_gather<<<nwB, 256>>>(N);                 // launch #4 on i=0 -> profiled
        k_upd<<<740, 128>>>(batch, Wa + i * 96 * 32, ba + i * 32, N);
        k_featmsg<<<740, 128>>>(Wg + i * 32, bg + i, Wf + i * 1024, bf + i * 32,
                                Wm + (lastS ? 0 : (i + 1) * 1024),
                                bm + (lastS ? 0 : (i + 1) * 32),
                                Wa1, ba1, N, lastS ? 0 : 1, lastS ? 1 : 0);
        k_pooltrans<<<G, 512>>>(Wt + i * 64 * 32, bt + i * 32,
                                Wa + (lastS ? 0 : (i + 1) * 96 * 32),
                                lastS ? 0 : 1, cur);
        cur ^= 1;
    }

    k_headsg<<<(G + 127) / 128, 128>>>(Wv, bv, Wa0, ba0, G, cur, out);
    k_a1<<<G, 256>>>(G, out);
}

// round 17
// speedup vs baseline: 1.5676x; 1.0020x over previous
#include <cuda_runtime.h>
#include <cuda_fp16.h>
#include <math_constants.h>

#define EMB 32
#define MAXN 200704
#define MAXE 3201024
#define MAXG 512
#define FULL 0xffffffffu

// ---------------- scratch ----------------
__device__ float    g_x[MAXN * EMB];
__device__ __align__(16) __half g_mh[MAXN * EMB];    // messages (fp16)
__device__ __align__(16) __half g_aggh[MAXN * EMB];  // gather-max result (fp16)
__device__ float    g_feat[MAXN * EMB];
__device__ float    g_gl[MAXN];           // gate logit
__device__ float    g_al[MAXN];           // a1 logit
__device__ float    g_e[MAXN];
__device__ float    g_xgA[MAXG * EMB];
__device__ float    g_xgB[MAXG * EMB];
__device__ float    g_xgdot[MAXG * EMB];  // per-graph xg @ Wa[32:64] (next step)
__device__ int      g_deg[MAXN];          // zero at load; re-zeroed by k_scan
__device__ int      g_row[MAXN + 1];
__device__ int      g_cur[MAXN];
__device__ int      g_csr[MAXE];          // BYTE offsets (src*64) into g_mh
__device__ int      g_part[1024];
__device__ int      g_gs[MAXG + 1];
__device__ int      g_ctr;
__device__ int      g_rel;                // release flag for spin-scan

__device__ __forceinline__ float lrelu(float v) { return v > 0.f ? v : 0.01f * v; }

__device__ __forceinline__ __half2 hmax2s(__half2 a, int o) {
    unsigned u = __shfl_xor_sync(FULL, *(unsigned*)&a, o);
    return __hmax2(a, *(__half2*)&u);
}

// ---------------- setup: hist || pre || embed+msg0 (grid-partitioned) ----------------
__global__ __launch_bounds__(256) void k_setup(
        const float* __restrict__ nf, const float* __restrict__ We,
        const float* __restrict__ be, const float* __restrict__ Wm,
        const float* __restrict__ bm, const int* __restrict__ ei,
        const int* __restrict__ batch, int N, int E, int G, int eB, int nB, int mB) {
    int b = blockIdx.x;
    int tid = threadIdx.x;
    if (b < eB) {                       // ---- hist (deg starts zero) ----
        int e = b * 256 + tid;
        if (e < E) atomicAdd(&g_deg[ei[E + e]], 1);
        return;
    }
    b -= eB;
    if (b < nB) {                       // ---- pre: graph offsets, zeroing ----
        int n = b * 256 + tid;
        if (n == 0) { g_ctr = 0; g_rel = 0; g_row[N] = E; }
        if (n < G * EMB) { g_xgA[n] = 0.f; g_xgB[n] = 0.f; g_xgdot[n] = 0.f; }
        if (n >= N) return;
        int bb = batch[n];
        int bp = (n == 0) ? -1 : batch[n - 1];
        for (int g = bp + 1; g <= bb; g++) g_gs[g] = n;
        if (n == N - 1) for (int g = bb + 1; g <= G; g++) g_gs[g] = N;
        return;
    }
    b -= nB;                            // ---- fused embed + msg0 ----
    int lane = tid & 31;
    float wE[32], bE[32], wm[32];
#pragma unroll
    for (int k = 0; k < 32; k++) { wE[k] = We[k]; bE[k] = be[k]; wm[k] = Wm[k * 32 + lane]; }
    float bmv = bm[lane];
    int warp = (b * 256 + tid) >> 5;
    int nwarps = mB * 8;
    for (int n = warp; n < N; n += nwarps) {
        float f = __ldg(&nf[n]);
        g_x[n * 32 + lane] = lrelu(f * wE[lane] + bE[lane]);
        float a0 = bmv, a1 = 0.f, a2 = 0.f, a3 = 0.f;
#pragma unroll
        for (int k = 0; k < 32; k += 4) {
            a0 += lrelu(f * wE[k + 0] + bE[k + 0]) * wm[k + 0];
            a1 += lrelu(f * wE[k + 1] + bE[k + 1]) * wm[k + 1];
            a2 += lrelu(f * wE[k + 2] + bE[k + 2]) * wm[k + 2];
            a3 += lrelu(f * wE[k + 3] + bE[k + 3]) * wm[k + 3];
        }
        g_mh[n * 32 + lane] = __float2half(lrelu((a0 + a1) + (a2 + a3)));
    }
}

// ---------------- single-pass scan with wide release ----------------
__global__ __launch_bounds__(512) void k_scan(int N, int nb) {
    __shared__ int sm[512];
    __shared__ int sp[512];
    __shared__ bool last;
    int t = threadIdx.x, b = blockIdx.x;
    int i = b * 512 + t;
    int v = (i < N) ? g_deg[i] : 0;
    sm[t] = v;
    __syncthreads();
    for (int off = 1; off < 512; off <<= 1) {
        int a = (t >= off) ? sm[t - off] : 0;
        __syncthreads();
        sm[t] += a;
        __syncthreads();
    }
    if (t == 0) {
        g_part[b] = sm[511];
        __threadfence();
        int old = atomicAdd(&g_ctr, 1);
        last = (old == nb - 1);
    }
    __syncthreads();
    if (last) {
        int pv = (t < nb) ? g_part[t] : 0;
        sp[t] = pv;
        __syncthreads();
        for (int off = 1; off < 512; off <<= 1) {
            int a = (t >= off) ? sp[t - off] : 0;
            __syncthreads();
            sp[t] += a;
            __syncthreads();
        }
        if (t < nb) g_part[t] = sp[t] - pv;
        __threadfence();
        if (t == 0) ((volatile int*)&g_rel)[0] = 1;
    } else {
        if (t == 0) {
            while (((volatile int*)&g_rel)[0] == 0) { }
        }
        __syncthreads();
        __threadfence();
    }
    int base = ((volatile int*)g_part)[b];
    if (i < N) {
        int r = base + sm[t] - v;
        g_row[i] = r;
        g_cur[i] = r;
        g_deg[i] = 0;
    }
}

__global__ void k_scatter(const int* __restrict__ ei, int E) {
    int e = blockIdx.x * blockDim.x + threadIdx.x;
    if (e >= E) return;
    int s = __ldg(&ei[e]);
    int d = __ldg(&ei[E + e]);
    int pos = atomicAdd(&g_cur[d], 1);
    g_csr[pos] = s << 6;          // byte offset into g_mh (64 B per node row)
}

// ---------------- gather-max (standalone, high occupancy) ----------------
// warp per node; lane = edge-slot(0..7) x 16B-chunk(0..3); fp16 maxima
__global__ void k_gather(int N) {
    int t = blockIdx.x * blockDim.x + threadIdx.x;
    int n = t >> 5;
    if (n >= N) return;
    int lane = t & 31;
    int eg = lane >> 2;
    int ch = lane & 3;
    const char* mbase = (const char*)g_mh + ch * 16;
    int base = g_row[n];
    int deg = g_row[n + 1] - base;
    __half2 ninf = __float2half2_rn(-CUDART_INF_F);
    __half2 m0 = ninf, m1 = ninf, m2 = ninf, m3 = ninf;
    const int* csr = g_csr + base;
    for (int j = eg; j < deg; j += 8) {       // no inner predicate
        int off = __ldg(&csr[j]);
        uint4 v = *(const uint4*)(mbase + off);
        m0 = __hmax2(m0, *(__half2*)&v.x);
        m1 = __hmax2(m1, *(__half2*)&v.y);
        m2 = __hmax2(m2, *(__half2*)&v.z);
        m3 = __hmax2(m3, *(__half2*)&v.w);
    }
#pragma unroll
    for (int o = 4; o <= 16; o <<= 1) {
        m0 = hmax2s(m0, o); m1 = hmax2s(m1, o);
        m2 = hmax2s(m2, o); m3 = hmax2s(m3, o);
    }
    if (eg == 0) {
        uint4 r;
        if (deg > 0) {
            r.x = *(unsigned*)&m0; r.y = *(unsigned*)&m1;
            r.z = *(unsigned*)&m2; r.w = *(unsigned*)&m3;
        } else {
            r.x = r.y = r.z = r.w = 0u;
        }
        *(uint4*)(g_aggh + n * 32 + ch * 8) = r;
    }
}

// ---------------- update MLP (lean: w[64] + precomputed xgdot) ----------------
// x = lrelu(x@Wa[0:32] + agg@Wa[64:96] + xgdot[batch] + ba) + x
__global__ __launch_bounds__(128) void k_upd(const int* __restrict__ batch,
                                             const float* __restrict__ Wa,
                                             const float* __restrict__ ba,
                                             int N) {
    int lane = threadIdx.x & 31;
    float w[64];
#pragma unroll
    for (int k = 0; k < 32; k++) w[k] = Wa[k * 32 + lane];             // x rows
#pragma unroll
    for (int k = 0; k < 32; k++) w[32 + k] = Wa[(64 + k) * 32 + lane]; // agg rows
    float bv = ba[lane];
    int warp = (blockIdx.x * blockDim.x + threadIdx.x) >> 5;
    int nwarps = (gridDim.x * blockDim.x) >> 5;
    for (int n = warp; n < N; n += nwarps) {
        int gidx = __ldg(&batch[n]);
        float a0 = bv + __ldg(&g_xgdot[gidx * 32 + lane]);
        float a1 = 0.f, a2 = 0.f, a3 = 0.f;
        const float4* xr = (const float4*)(g_x + n * 32);
        const uint4* ar = (const uint4*)(g_aggh + n * 32);
#pragma unroll
        for (int c = 0; c < 8; c++) {
            float4 v = xr[c];
            a0 += v.x * w[c * 4 + 0];
            a1 += v.y * w[c * 4 + 1];
            a2 += v.z * w[c * 4 + 2];
            a3 += v.w * w[c * 4 + 3];
        }
#pragma unroll
        for (int c = 0; c < 4; c++) {
            uint4 u = ar[c];
            float2 f0 = __half22float2(*(__half2*)&u.x);
            float2 f1 = __half22float2(*(__half2*)&u.y);
            float2 f2 = __half22float2(*(__half2*)&u.z);
            float2 f3 = __half22float2(*(__half2*)&u.w);
            a0 += f0.x * w[32 + c * 8 + 0];
            a1 += f0.y * w[32 + c * 8 + 1];
            a2 += f1.x * w[32 + c * 8 + 2];
            a3 += f1.y * w[32 + c * 8 + 3];
            a0 += f2.x * w[32 + c * 8 + 4];
            a1 += f2.y * w[32 + c * 8 + 5];
            a2 += f3.x * w[32 + c * 8 + 6];
            a3 += f3.y * w[32 + c * 8 + 7];
        }
        float xv = g_x[n * 32 + lane];
        g_x[n * 32 + lane] = lrelu((a0 + a1) + (a2 + a3)) + xv;
    }
}

// fused: feat = lrelu(x@Wf+bf); gate logit; next-step msg (fp16); optional a1 logit
__global__ __launch_bounds__(128) void k_featmsg(const float* __restrict__ Wg,
                                                 const float* __restrict__ bg,
                                                 const float* __restrict__ Wf,
                                                 const float* __restrict__ bf,
                                                 const float* __restrict__ Wm,
                                                 const float* __restrict__ bm,
                                                 const float* __restrict__ Wa1,
                                                 const float* __restrict__ ba1,
                                                 int N, int do_msg, int do_a1) {
    int lane = threadIdx.x & 31;
    int ch = lane & 7;
    float wf[32], wm[32], wg4[4], wa4[4];
#pragma unroll
    for (int k = 0; k < 32; k++) {
        wf[k] = Wf[k * 32 + lane];
        wm[k] = do_msg ? Wm[k * 32 + lane] : 0.f;
    }
#pragma unroll
    for (int k = 0; k < 4; k++) {
        wg4[k] = Wg[ch * 4 + k];
        wa4[k] = do_a1 ? Wa1[ch * 4 + k] : 0.f;
    }
    float bfv = bf[lane];
    float bmv = do_msg ? bm[lane] : 0.f;
    float bgv = bg[0];
    float ba1v = do_a1 ? ba1[0] : 0.f;
    int warp = (blockIdx.x * blockDim.x + threadIdx.x) >> 5;
    int nwarps = (gridDim.x * blockDim.x) >> 5;
    for (int n = warp; n < N; n += nwarps) {
        const float4* xr = (const float4*)(g_x + n * 32);
        float a0 = bfv, a1 = 0.f, a2 = 0.f, a3 = 0.f;
        float q0 = bmv, q1 = 0.f, q2 = 0.f, q3 = 0.f;
        float p = 0.f, pa = 0.f;
#pragma unroll
        for (int c = 0; c < 8; c++) {
            float4 v = xr[c];
            a0 += v.x * wf[c * 4 + 0];
            a1 += v.y * wf[c * 4 + 1];
            a2 += v.z * wf[c * 4 + 2];
            a3 += v.w * wf[c * 4 + 3];
            if (do_msg) {
                q0 += v.x * wm[c * 4 + 0];
                q1 += v.y * wm[c * 4 + 1];
                q2 += v.z * wm[c * 4 + 2];
                q3 += v.w * wm[c * 4 + 3];
            }
            if (c == ch) {
                p  = v.x * wg4[0] + v.y * wg4[1] + v.z * wg4[2] + v.w * wg4[3];
                if (do_a1)
                    pa = v.x * wa4[0] + v.y * wa4[1] + v.z * wa4[2] + v.w * wa4[3];
            }
        }
        g_feat[n * 32 + lane] = lrelu((a0 + a1) + (a2 + a3));
        if (do_msg)
            g_mh[n * 32 + lane] = __float2half(lrelu((q0 + q1) + (q2 + q3)));
#pragma unroll
        for (int o = 1; o <= 4; o <<= 1) {
            p += __shfl_xor_sync(FULL, p, o);
            if (do_a1) pa += __shfl_xor_sync(FULL, pa, o);
        }
        if (lane == 0) {
            g_gl[n] = p + bgv;
            if (do_a1) g_al[n] = pa + ba1v;
        }
    }
}

// block-per-graph: segment softmax + attention pooling + transform;
// also precomputes g_xgdot for the NEXT step's update MLP.
__global__ void k_pooltrans(const float* __restrict__ Wt, const float* __restrict__ bt,
                            const float* __restrict__ WaN, int do_next, int cur) {
    __shared__ float sred[16];
    __shared__ float sfac[16][32];
    __shared__ float smx, sinv;
    __shared__ float spooled[32];
    __shared__ float sxg[32];
    __shared__ float sxgn[32];
    int g = blockIdx.x;
    int tid = threadIdx.x;
    int wid = tid >> 5, lane = tid & 31;
    int s = g_gs[g], e2 = g_gs[g + 1];

    float lmax = -CUDART_INF_F;
    for (int n = s + tid; n < e2; n += 512) lmax = fmaxf(lmax, g_gl[n]);
#pragma unroll
    for (int o = 16; o; o >>= 1) lmax = fmaxf(lmax, __shfl_xor_sync(FULL, lmax, o));
    if (lane == 0) sred[wid] = lmax;
    __syncthreads();
    if (tid == 0) {
        float m = sred[0];
#pragma unroll
        for (int w = 1; w < 16; w++) m = fmaxf(m, sred[w]);
        smx = m;
    }
    __syncthreads();
    float mx = smx;

    float facc = 0.f, se = 0.f;
    for (int n = s + wid; n < e2; n += 16) {
        float ev = __expf(g_gl[n] - mx);
        facc += ev * g_feat[n * 32 + lane];
        if (lane == 0) se += ev;
    }
    sfac[wid][lane] = facc;
    if (lane == 0) sred[wid] = se;
    __syncthreads();
    if (wid == 0) {
        float p = 0.f;
#pragma unroll
        for (int w = 0; w < 16; w++) p += sfac[w][lane];
        spooled[lane] = p;
        if (lane == 0) {
            float t = 0.f;
#pragma unroll
            for (int w = 0; w < 16; w++) t += sred[w];
            sinv = t > 0.f ? 1.f / t : 0.f;
        }
        const float* xgc = cur ? g_xgB : g_xgA;
        sxg[lane] = xgc[g * 32 + lane];
    }
    __syncthreads();

    if (tid < 32) {
        int c = tid;
        float inv = sinv;
        float acc = bt[c];
#pragma unroll
        for (int k = 0; k < 32; k++) acc += (spooled[k] * inv) * Wt[k * 32 + c];
#pragma unroll
        for (int k = 0; k < 32; k++) acc += sxg[k] * Wt[(32 + k) * 32 + c];
        float* xgn = cur ? g_xgA : g_xgB;
        float xnew = lrelu(acc) + sxg[c];
        xgn[g * 32 + c] = xnew;
        sxgn[c] = xnew;
        __syncwarp();
        if (do_next) {      // xgdot[c] = sum_k xg_next[k] * WaN[(32+k)*32+c]
            float d0 = 0.f, d1 = 0.f, d2 = 0.f, d3 = 0.f;
#pragma unroll
            for (int k = 0; k < 32; k += 4) {
                d0 += sxgn[k + 0] * __ldg(&WaN[(32 + k + 0) * 32 + c]);
                d1 += sxgn[k + 1] * __ldg(&WaN[(32 + k + 1) * 32 + c]);
                d2 += sxgn[k + 2] * __ldg(&WaN[(32 + k + 2) * 32 + c]);
                d3 += sxgn[k + 3] * __ldg(&WaN[(32 + k + 3) * 32 + c]);
            }
            g_xgdot[g * 32 + c] = (d0 + d1) + (d2 + d3);
        }
    }
}

__global__ void k_headsg(const float* __restrict__ Wv, const float* __restrict__ bv,
                         const float* __restrict__ Wa0, const float* __restrict__ ba0,
                         int G, int cur, float* __restrict__ out) {
    int g = blockIdx.x * blockDim.x + threadIdx.x;
    if (g >= G) return;
    const float* xg = cur ? g_xgB : g_xgA;
    float v = bv[0], l0 = ba0[0], l1 = ba0[1];
#pragma unroll
    for (int k = 0; k < 32; k++) {
        float xx = xg[g * 32 + k];
        v += xx * Wv[k];
        l0 += xx * Wa0[k * 2];
        l1 += xx * Wa0[k * 2 + 1];
    }
    out[g] = v;
    float mxv = fmaxf(l0, l1);
    float e0 = __expf(l0 - mxv), e1 = __expf(l1 - mxv);
    float ssum = e0 + e1;
    out[G + g * 2] = e0 / ssum;
    out[G + g * 2 + 1] = e1 / ssum;
}

// final a1 segment softmax over precomputed logits g_al
__global__ void k_a1(int G, float* __restrict__ out) {
    __shared__ float sred[8];
    __shared__ float smx, sinv;
    int g = blockIdx.x;
    int tid = threadIdx.x;
    int wid = tid >> 5, lane = tid & 31;
    int s = g_gs[g], e2 = g_gs[g + 1];

    float lmax = -CUDART_INF_F;
    for (int n = s + tid; n < e2; n += 256) lmax = fmaxf(lmax, g_al[n]);
#pragma unroll
    for (int o = 16; o; o >>= 1) lmax = fmaxf(lmax, __shfl_xor_sync(FULL, lmax, o));
    if (lane == 0) sred[wid] = lmax;
    __syncthreads();
    if (tid == 0) {
        float m = sred[0];
#pragma unroll
        for (int w = 1; w < 8; w++) m = fmaxf(m, sred[w]);
        smx = m;
    }
    __syncthreads();
    float mx = smx;

    float ps = 0.f;
    for (int n = s + tid; n < e2; n += 256) {
        float ev = __expf(g_al[n] - mx);
        g_e[n] = ev;
        ps += ev;
    }
#pragma unroll
    for (int o = 16; o; o >>= 1) ps += __shfl_xor_sync(FULL, ps, o);
    if (lane == 0) sred[wid] = ps;
    __syncthreads();
    if (tid == 0) {
        float t = 0.f;
#pragma unroll
        for (int w = 0; w < 8; w++) t += sred[w];
        sinv = t > 0.f ? 1.f / t : 0.f;
    }
    __syncthreads();
    float inv = sinv;
    for (int n = s + tid; n < e2; n += 256)
        out[3 * G + n] = g_e[n] * inv;
}

// ---------------- launcher (two-stream overlap: pooltrans || next gather) -----
extern "C" void kernel_launch(void* const* d_in, const int* in_sizes, int n_in,
                              void* d_out, int out_size) {
    const float* nf   = (const float*)d_in[0];
    const int*   ei   = (const int*)d_in[1];
    const int*   batch= (const int*)d_in[2];
    const float* We   = (const float*)d_in[4];
    const float* be   = (const float*)d_in[5];
    const float* Wm   = (const float*)d_in[6];
    const float* bm   = (const float*)d_in[7];
    const float* Wa   = (const float*)d_in[8];
    const float* ba   = (const float*)d_in[9];
    const float* Wg   = (const float*)d_in[10];
    const float* bg   = (const float*)d_in[11];
    const float* Wf   = (const float*)d_in[12];
    const float* bf   = (const float*)d_in[13];
    const float* Wt   = (const float*)d_in[14];
    const float* bt   = (const float*)d_in[15];
    const float* Wv   = (const float*)d_in[16];
    const float* bv   = (const float*)d_in[17];
    const float* Wa0  = (const float*)d_in[18];
    const float* ba0  = (const float*)d_in[19];
    const float* Wa1  = (const float*)d_in[20];
    const float* ba1  = (const float*)d_in[21];
    float* out = (float*)d_out;

    int N = in_sizes[0];
    int E = in_sizes[1] / 2;
    int G = (out_size - N) / 3;
    int S = in_sizes[6] / (EMB * EMB);

    int eB   = (E + 255) / 256;
    int nB   = (N + 255) / 256;
    int nwB  = (N * 32 + 255) / 256;
    int mB   = 296;
    int nsb  = (N + 511) / 512;

    // one-time side-stream + events (host resources, not device memory)
    static cudaStream_t s1 = 0;
    static cudaEvent_t evFeat = 0, evPool = 0, evJoin = 0;
    if (s1 == 0) {
        cudaStreamCreateWithFlags(&s1, cudaStreamNonBlocking);
        cudaEventCreateWithFlags(&evFeat, cudaEventDisableTiming);
        cudaEventCreateWithFlags(&evPool, cudaEventDisableTiming);
        cudaEventCreateWithFlags(&evJoin, cudaEventDisableTiming);
    }

    k_setup<<<eB + nB + mB, 256>>>(nf, We, be, Wm, bm, ei, batch, N, E, G, eB, nB, mB);
    k_scan<<<nsb, 512>>>(N, nsb);
    k_scatter<<<eB, 256>>>(ei, E);

    int cur = 0;
    for (int i = 0; i < S; i++) {
        int lastS = (i == S - 1);
        k_gather<<<nwB, 256>>>(N);             // overlaps with pooltrans(i-1) on s1
        if (i > 0) cudaStreamWaitEvent(0, evPool, 0);   // upd needs g_xgdot
        k_upd<<<740, 128>>>(batch, Wa + i * 96 * 32, ba + i * 32, N);
        k_featmsg<<<740, 128>>>(Wg + i * 32, bg + i, Wf + i * 1024, bf + i * 32,
                                Wm + (lastS ? 0 : (i + 1) * 1024),
                                bm + (lastS ? 0 : (i + 1) * 32),
                                Wa1, ba1, N, lastS ? 0 : 1, lastS ? 1 : 0);
        cudaEventRecord(evFeat, 0);
        cudaStreamWaitEvent(s1, evFeat, 0);
        k_pooltrans<<<G, 512, 0, s1>>>(Wt + i * 64 * 32, bt + i * 32,
                                       Wa + (lastS ? 0 : (i + 1) * 96 * 32),
                                       lastS ? 0 : 1, cur);
        cudaEventRecord(evPool, s1);
        cur ^= 1;
    }

    // tails: headsg (needs final xg) chains on s1; a1 (needs g_al) on stream 0
    k_headsg<<<(G + 127) / 128, 128, 0, s1>>>(Wv, bv, Wa0, ba0, G, cur, out);
    k_a1<<<G, 256>>>(G, out);
    cudaEventRecord(evJoin, s1);
    cudaStreamWaitEvent(0, evJoin, 0);     // join: capture DAG ends on stream 0
}